// round 17
// baseline (speedup 1.0000x reference)
#include <cuda_runtime.h>
#include <cuda_fp16.h>
#include <math.h>
#include <stdint.h>

// Problem constants
#define S_LEN 1024
#define BATCH 2
#define DMODEL 1024
#define HEADS 16
#define HDIM 64
#define TLEN 2048
#define FFDIM 4096
#define ROWS_X (S_LEN * BATCH)     // 2048
#define ROWS_T (TLEN * BATCH)      // 4096
#define NSPLIT 4
#define PERSIST_CTAS 296

// ---------------- scratch buffers (device globals) ---------------------------
__device__ float g_t [ROWS_X * DMODEL];
__device__ float g_t2[ROWS_X * DMODEL];
__device__ float g_u [ROWS_X * DMODEL];
// split-KV flash partials
__device__ float g_po [NSPLIT * ROWS_X * DMODEL];
__device__ float g_ml [NSPLIT * ROWS_X * HEADS * 2];
// fp16 tensors
__device__ __half g_xh  [ROWS_X * DMODEL];
__device__ __half g_memh[ROWS_X * DMODEL];
__device__ __half g_ph  [ROWS_T * DMODEL];
__device__ __half g_wqh [DMODEL * DMODEL];
__device__ __half g_wkeh[DMODEL * DMODEL];
__device__ __half g_wkrh[DMODEL * DMODEL];
__device__ __half g_wvh [DMODEL * DMODEL];
__device__ __half g_wch [DMODEL * DMODEL];
__device__ __half g_w1h [FFDIM * DMODEL];
__device__ __half g_w2h [DMODEL * FFDIM];
__device__ __half g_qh  [ROWS_X * DMODEL];
__device__ __half g_keh [ROWS_T * DMODEL];
__device__ __half g_krh [ROWS_T * DMODEL];
__device__ __half g_avh [ROWS_X * DMODEL];
__device__ __half g_uh  [ROWS_X * DMODEL];
__device__ __half g_h1h [ROWS_X * FFDIM];
// flash-prep outputs (fp16 KK; V written directly by projection; fp32 bias/8)
__device__ __half g_kkh [BATCH * HEADS * TLEN * HDIM];
__device__ __half g_vh  [BATCH * HEADS * TLEN * HDIM];
__device__ float  g_bias[BATCH * HEADS * TLEN];

// ---------------- common PTX helpers ----------------------------------------
__device__ __forceinline__ void cp_async16(uint32_t saddr, const void* gptr) {
    asm volatile("cp.async.cg.shared.global [%0], [%1], 16;\n"
                 :: "r"(saddr), "l"(gptr));
}
__device__ __forceinline__ void cp_commit() {
    asm volatile("cp.async.commit_group;\n");
}
template <int N>
__device__ __forceinline__ void cp_wait() {
    asm volatile("cp.async.wait_group %0;\n" :: "n"(N));
}
__device__ __forceinline__ void mma_f16(float* d, const uint32_t* a, const uint32_t* b) {
    asm volatile(
        "mma.sync.aligned.m16n8k16.row.col.f32.f16.f16.f32 "
        "{%0,%1,%2,%3}, {%4,%5,%6,%7}, {%8,%9}, {%0,%1,%2,%3};\n"
        : "+f"(d[0]), "+f"(d[1]), "+f"(d[2]), "+f"(d[3])
        : "r"(a[0]), "r"(a[1]), "r"(a[2]), "r"(a[3]), "r"(b[0]), "r"(b[1]));
}
__device__ __forceinline__ void ldm_x4(uint32_t* r, uint32_t addr) {
    asm volatile("ldmatrix.sync.aligned.m8n8.x4.shared.b16 {%0,%1,%2,%3}, [%4];"
                 : "=r"(r[0]), "=r"(r[1]), "=r"(r[2]), "=r"(r[3]) : "r"(addr));
}
__device__ __forceinline__ void ldm_x4_t(uint32_t* r, uint32_t addr) {
    asm volatile("ldmatrix.sync.aligned.m8n8.x4.trans.shared.b16 {%0,%1,%2,%3}, [%4];"
                 : "=r"(r[0]), "=r"(r[1]), "=r"(r[2]), "=r"(r[3]) : "r"(addr));
}

// ---------------- fp32 -> fp16 conversion (merged segments) ------------------
#define MAXSEG 10
struct CvtSegs {
    const float* src[MAXSEG];
    __half*      dst[MAXSEG];
    int          end8[MAXSEG];
    int          nseg;
};

__global__ void __launch_bounds__(256)
cvt_all_kernel(CvtSegs segs, int total8)
{
    int idx = blockIdx.x * 256 + threadIdx.x;
    if (idx >= total8) return;
    int s = 0;
#pragma unroll
    for (int i = 0; i < MAXSEG; i++)
        if (i < segs.nseg && idx >= segs.end8[i]) s = i + 1;
    const int off = idx - (s ? segs.end8[s - 1] : 0);

    const float4* s4 = (const float4*)(segs.src[s] + (size_t)off * 8);
    float4 a = s4[0], b = s4[1];
    __half2 h[4];
    h[0] = __floats2half2_rn(a.x, a.y);
    h[1] = __floats2half2_rn(a.z, a.w);
    h[2] = __floats2half2_rn(b.x, b.y);
    h[3] = __floats2half2_rn(b.z, b.w);
    *(uint4*)(segs.dst[s] + (size_t)off * 8) = *(uint4*)h;
}

// ---------------- fp16 tensor-core GEMM (BK=64, 3-stage, PERSISTENT) ---------
// vmask: bit z set -> Ch is the flash V buffer [b,h,t,64]; voff = t offset.
struct GemmPtrs {
    const __half* A[7];
    const __half* W[7];
    float*        C[7];
    __half*       Ch[7];
    const float*  bias[7];
    int           voff[7];
};

#define HROW 144u                      // smem row stride in bytes (64h data+pad)
#define TILE16 (128u * HROW)           // 18432 B per operand tile (K=64)
#define STAGE16 (2u * TILE16)          // 36864 B per stage
#define GEMM16_SMEM (3 * 36864)        // 110592 B (3 stages)

__global__ void __launch_bounds__(256)
gemm16_kernel(GemmPtrs ptrs, int M, int N, int Klen, int Kstride, int act,
              int vmask, int ntx, int nty, int ntz)
{
    extern __shared__ char smem[];
    const uint32_t sbase = (uint32_t)__cvta_generic_to_shared(smem);

    const int tid = threadIdx.x;
    const int lane = tid & 31, wrp = tid >> 5;
    const int wm = wrp & 1, wn = wrp >> 1;
    const int q = lane >> 2, r = lane & 3;
    const int alr = lane & 15, alc = lane >> 4;
    const int bg = lane >> 3,  blr = lane & 7;

    const int ntiles = ntx * nty * ntz;
    const int KT = Klen >> 6;

    for (int tile = blockIdx.x; tile < ntiles; tile += gridDim.x) {
        const int z   = tile / (ntx * nty);
        const int rem = tile % (ntx * nty);
        const int m0 = (rem / ntx) * 128;
        const int n0 = (rem % ntx) * 128;

        const __half* A    = ptrs.A[z];
        const __half* W    = ptrs.W[z];
        float*        C    = ptrs.C[z];
        __half*       Ch   = ptrs.Ch[z];
        const float*  bias = ptrs.bias[z];
        const bool    vfuse = (vmask >> z) & 1;
        const int     voff  = ptrs.voff[z];

        __syncthreads();   // previous tile's smem reads complete before refill

        float acc[4][4][4];
#pragma unroll
        for (int i = 0; i < 4; i++)
#pragma unroll
            for (int j = 0; j < 4; j++)
#pragma unroll
                for (int e = 0; e < 4; e++) acc[i][j][e] = 0.f;

        auto issue = [&](int t) {          // K-chunk index (64 halves); stage t%3
            const uint32_t so = sbase + (uint32_t)(t % 3) * STAGE16;
            const int k0 = t << 6;
#pragma unroll
            for (int i = 0; i < 4; i++) {
                int id = tid + i * 256;
                int row = id >> 3, c = id & 7;
                uint32_t d = (uint32_t)row * HROW + (uint32_t)c * 16u;
                cp_async16(so + d,          A + (size_t)(m0 + row) * Kstride + k0 + c * 8);
                cp_async16(so + TILE16 + d, W + (size_t)(n0 + row) * Kstride + k0 + c * 8);
            }
        };

        issue(0);
        cp_commit();
        if (KT > 1) { issue(1); cp_commit(); }

        for (int kt = 0; kt < KT; kt++) {
            if (kt == KT - 1) { cp_wait<0>(); } else { cp_wait<1>(); }
            __syncthreads();
            if (kt + 2 < KT) { issue(kt + 2); cp_commit(); }

            const uint32_t aBase = sbase + (uint32_t)(kt % 3) * STAGE16;
            const uint32_t bBase = aBase + TILE16;

#pragma unroll
            for (int ks = 0; ks < 4; ks++) {
                uint32_t afr[4][4];
#pragma unroll
                for (int mt = 0; mt < 4; mt++) {
                    uint32_t addr = aBase +
                        (uint32_t)(wm * 64 + mt * 16 + alr) * HROW +
                        (uint32_t)(ks * 32 + alc * 16);
                    ldm_x4(afr[mt], addr);
                }
                uint32_t bfr[4][2];
#pragma unroll
                for (int ntp = 0; ntp < 2; ntp++) {
                    uint32_t addr = bBase +
                        (uint32_t)(wn * 32 + ntp * 16 + (bg >> 1) * 8 + blr) * HROW +
                        (uint32_t)(ks * 32 + (bg & 1) * 16);
                    uint32_t tmp[4];
                    ldm_x4(tmp, addr);
                    bfr[ntp * 2 + 0][0] = tmp[0]; bfr[ntp * 2 + 0][1] = tmp[1];
                    bfr[ntp * 2 + 1][0] = tmp[2]; bfr[ntp * 2 + 1][1] = tmp[3];
                }
#pragma unroll
                for (int mt = 0; mt < 4; mt++)
#pragma unroll
                    for (int nt = 0; nt < 4; nt++)
                        mma_f16(acc[mt][nt], afr[mt], bfr[nt]);
            }
        }

#pragma unroll
        for (int mt = 0; mt < 4; mt++) {
            const int row0 = m0 + wm * 64 + mt * 16 + q;
#pragma unroll
            for (int nt = 0; nt < 4; nt++) {
                const int col = n0 + wn * 32 + nt * 8 + r * 2;
                float b0 = bias ? bias[col]     : 0.f;
                float b1 = bias ? bias[col + 1] : 0.f;
                float v0 = acc[mt][nt][0] + b0, v1 = acc[mt][nt][1] + b1;
                float v2 = acc[mt][nt][2] + b0, v3 = acc[mt][nt][3] + b1;
                if (act == 1) {
                    v0 = fmaxf(v0, 0.f); v1 = fmaxf(v1, 0.f);
                    v2 = fmaxf(v2, 0.f); v3 = fmaxf(v3, 0.f);
                }
                if (C) {
                    *(float2*)(C + (size_t)row0 * N + col)       = make_float2(v0, v1);
                    *(float2*)(C + (size_t)(row0 + 8) * N + col) = make_float2(v2, v3);
                }
                if (Ch) {
                    if (vfuse) {
                        const int h = col >> 6, d = col & 63;
                        const int t0 = (row0 >> 1), b0r = row0 & 1;
                        const int t1 = ((row0 + 8) >> 1), b1r = (row0 + 8) & 1;
                        *(__half2*)(Ch + (((size_t)(b0r * HEADS + h) * TLEN + voff + t0) * HDIM + d))
                            = __floats2half2_rn(v0, v1);
                        *(__half2*)(Ch + (((size_t)(b1r * HEADS + h) * TLEN + voff + t1) * HDIM + d))
                            = __floats2half2_rn(v2, v3);
                    } else {
                        *(__half2*)(Ch + (size_t)row0 * N + col)       = __floats2half2_rn(v0, v1);
                        *(__half2*)(Ch + (size_t)(row0 + 8) * N + col) = __floats2half2_rn(v2, v3);
                    }
                }
            }
        }
    }
}

// ---------------- prep (fp16 in): KK = ke+kr, bias = (u.ke+v.kr)/8 -----------
__global__ void __launch_bounds__(256)
prep_kernel(const __half* __restrict__ keh, const __half* __restrict__ krh,
            const float* __restrict__ ub, const float* __restrict__ vb,
            __half* __restrict__ kkh, float* __restrict__ biasO)
{
    const int row = blockIdx.x;          // = t*BATCH + b
    const int t = row / BATCH, b = row % BATCH;
    const int tid = threadIdx.x;
    const int h = tid >> 4, l16 = tid & 15, d0 = l16 * 4;

    const size_t src = (size_t)row * DMODEL + h * HDIM + d0;
    uint2 ke2 = *(const uint2*)(keh + src);
    uint2 kr2 = *(const uint2*)(krh + src);

    float2 ke01 = __half22float2(*(__half2*)&ke2.x);
    float2 ke23 = __half22float2(*(__half2*)&ke2.y);
    float2 kr01 = __half22float2(*(__half2*)&kr2.x);
    float2 kr23 = __half22float2(*(__half2*)&kr2.y);

    const size_t dst = ((size_t)(b * HEADS + h) * TLEN + t) * HDIM + d0;
    __half2 kk01 = __floats2half2_rn(ke01.x + kr01.x, ke01.y + kr01.y);
    __half2 kk23 = __floats2half2_rn(ke23.x + kr23.x, ke23.y + kr23.y);
    *(uint2*)(kkh + dst) = make_uint2(*(uint32_t*)&kk01, *(uint32_t*)&kk23);

    float4 u4 = *(const float4*)(ub + h * HDIM + d0);
    float4 w4 = *(const float4*)(vb + h * HDIM + d0);
    float bsum = u4.x * ke01.x + u4.y * ke01.y + u4.z * ke23.x + u4.w * ke23.y
               + w4.x * kr01.x + w4.y * kr01.y + w4.z * kr23.x + w4.w * kr23.y;
#pragma unroll
    for (int off = 8; off; off >>= 1)
        bsum += __shfl_xor_sync(0xffffffffu, bsum, off, 16);
    if (l16 == 0)
        biasO[(size_t)(b * HEADS + h) * TLEN + t] = bsum * 0.125f;  // pre-scaled
}

// ---------------- fp16 flash attention (split-KV x4, double-buffered) --------
#define QH_OFF 0u
#define PH_OFF 18432u
#define KK_OFF 36864u          // + buf*9216
#define V_OFF  55296u          // + buf*9216
#define BI_OFF 73728u          // + buf*256
#define KVBUF  9216u
#define FLASH_SMEM 74240
#define ML_HALF (ROWS_X * HEADS * 2)
#define PO_HALF ((size_t)ROWS_X * DMODEL)

__global__ void __launch_bounds__(256, 2)
flash16_kernel(const __half* __restrict__ qh,
               const __half* __restrict__ kkh,
               const __half* __restrict__ vhg,
               const float* __restrict__ biasG,
               float* __restrict__ poAll, float* __restrict__ mlAll)
{
    extern __shared__ char fsm[];
    const uint32_t sbase = (uint32_t)__cvta_generic_to_shared(fsm);
    __half* PhH = (__half*)(fsm + PH_OFF);

    const int xid = blockIdx.x;
    const int qb = 7 - (xid >> 2);       // heavy q-blocks first
    const int hf = xid & 3;
    const int h = blockIdx.y, b = blockIdx.z;
    const int tid = threadIdx.x;
    const int lane = tid & 31, wid = tid >> 5;
    const int q = lane >> 2, r = lane & 3;
    const int mw = wid * 16;
    const int alr = lane & 15, alc = lane >> 4;
    const int bg = lane >> 3,  blr = lane & 7;

    const int ntAll = 18 + 2 * qb;
    const int base = ntAll >> 2, rem = ntAll & 3;
    const int tstart = hf * base + min(hf, rem);
    const int tend   = tstart + base + (hf < rem ? 1 : 0);
    float* po  = poAll + (size_t)hf * PO_HALF;
    float* mlp = mlAll + (size_t)hf * ML_HALF;

    const size_t  bh   = (size_t)(b * HEADS + h) * TLEN;
    const __half* kkbh = kkh + bh * HDIM;
    const __half* vbh  = vhg + bh * HDIM;
    const float*  bibh = biasG + bh;

    auto issueQ = [&]() {
#pragma unroll
        for (int it = 0; it < 4; it++) {
            int idx = tid + it * 256;
            int row = idx >> 3, c = idx & 7;
            cp_async16(sbase + QH_OFF + (uint32_t)row * HROW + (uint32_t)c * 16u,
                       qh + ((size_t)((qb * 128 + row) * BATCH + b)) * DMODEL
                          + h * HDIM + c * 8);
        }
    };
    auto issueKV = [&](int t0, int buf) {
        const uint32_t kkB = sbase + KK_OFF + (uint32_t)buf * KVBUF;
        const uint32_t vB  = sbase + V_OFF  + (uint32_t)buf * KVBUF;
#pragma unroll
        for (int it = 0; it < 2; it++) {
            int idx = tid + it * 256;
            int row = idx >> 3, c = idx & 7;
            const uint32_t d = (uint32_t)row * HROW + (uint32_t)c * 16u;
            cp_async16(kkB + d, kkbh + (size_t)(t0 + row) * HDIM + c * 8);
            cp_async16(vB  + d, vbh  + (size_t)(t0 + row) * HDIM + c * 8);
        }
        if (tid < 16)
            cp_async16(sbase + BI_OFF + (uint32_t)(buf * 256 + tid * 16),
                       bibh + t0 + tid * 4);
    };

    issueQ();
    issueKV(tstart * 64, tstart & 1);
    cp_commit();

    float m0 = -1e30f, m1 = -1e30f, l0 = 0.f, l1 = 0.f;
    float O[8][4];
#pragma unroll
    for (int nt = 0; nt < 8; nt++)
#pragma unroll
        for (int e = 0; e < 4; e++) O[nt][e] = 0.f;

    const int srow0 = qb * 128 + mw + q;

    for (int tt = tstart; tt < tend; tt++) {
        const int t0 = tt * 64;
        const int buf = tt & 1;
        const bool more = (tt + 1 < tend);

        cp_wait<0>();
        __syncthreads();

        if (more) { issueKV(t0 + 64, buf ^ 1); cp_commit(); }

        const uint32_t kkB = sbase + KK_OFF + (uint32_t)buf * KVBUF;
        const uint32_t vB  = sbase + V_OFF  + (uint32_t)buf * KVBUF;
        const float* bS = (const float*)(fsm + BI_OFF + buf * 256);

        // ---- S = Q @ KK^T  (fp16 mma) --------------------------------------
        float sc[8][4];
#pragma unroll
        for (int nt = 0; nt < 8; nt++)
#pragma unroll
            for (int e = 0; e < 4; e++) sc[nt][e] = 0.f;

#pragma unroll
        for (int ks = 0; ks < 4; ks++) {
            uint32_t afr[4];
            ldm_x4(afr, sbase + QH_OFF + (uint32_t)(mw + alr) * HROW
                         + (uint32_t)(ks * 32 + alc * 16));
#pragma unroll
            for (int tb = 0; tb < 4; tb++) {
                uint32_t tmp[4];
                ldm_x4(tmp, kkB
                             + (uint32_t)(tb * 16 + (bg >> 1) * 8 + blr) * HROW
                             + (uint32_t)(ks * 32 + (bg & 1) * 16));
                mma_f16(sc[tb * 2],     afr, tmp);
                mma_f16(sc[tb * 2 + 1], afr, tmp + 2);
            }
        }

        // ---- bias(pre-scaled) + causal mask + online softmax ----------------
        const bool mt_ = (tt >= 16 + 2 * qb);
        float tmax0 = -1e30f, tmax1 = -1e30f;
#pragma unroll
        for (int nt = 0; nt < 8; nt++) {
            const int colb = nt * 8 + 2 * r;
            const float bi0 = bS[colb], bi1 = bS[colb + 1];
            float v0 = fmaf(sc[nt][0], 0.125f, bi0);
            float v1 = fmaf(sc[nt][1], 0.125f, bi1);
            float v2 = fmaf(sc[nt][2], 0.125f, bi0);
            float v3 = fmaf(sc[nt][3], 0.125f, bi1);
            if (mt_) {
                const int tc = t0 + colb;
                if (tc     > S_LEN + srow0)     v0 = -1e30f;
                if (tc + 1 > S_LEN + srow0)     v1 = -1e30f;
                if (tc     > S_LEN + srow0 + 8) v2 = -1e30f;
                if (tc + 1 > S_LEN + srow0 + 8) v3 = -1e30f;
            }
            sc[nt][0] = v0; sc[nt][1] = v1; sc[nt][2] = v2; sc[nt][3] = v3;
            tmax0 = fmaxf(tmax0, fmaxf(v0, v1));
            tmax1 = fmaxf(tmax1, fmaxf(v2, v3));
        }
        tmax0 = fmaxf(tmax0, __shfl_xor_sync(0xffffffffu, tmax0, 1));
        tmax0 = fmaxf(tmax0, __shfl_xor_sync(0xffffffffu, tmax0, 2));
        tmax1 = fmaxf(tmax1, __shfl_xor_sync(0xffffffffu, tmax1, 1));
        tmax1 = fmaxf(tmax1, __shfl_xor_sync(0xffffffffu, tmax1, 2));

        const float mnew0 = fmaxf(m0, tmax0);
        const float mnew1 = fmaxf(m1, tmax1);
        const float c0 = __expf(m0 - mnew0);
        const float c1 = __expf(m1 - mnew1);
        m0 = mnew0; m1 = mnew1;
        l0 *= c0; l1 *= c1;

        const bool doscale = !__all_sync(0xffffffffu, (c0 == 1.f) && (c1 == 1.f));

        float ps0 = 0.f, ps1 = 0.f;
#pragma unroll
        for (int nt = 0; nt < 8; nt++) {
            float p0 = __expf(sc[nt][0] - mnew0);
            float p1 = __expf(sc[nt][1] - mnew0);
            float p2 = __expf(sc[nt][2] - mnew1);
            float p3 = __expf(sc[nt][3] - mnew1);
            ps0 += p0 + p1; ps1 += p2 + p3;
            if (doscale) {
                O[nt][0] *= c0; O[nt][1] *= c0;
                O[nt][2] *= c1; O[nt][3] *= c1;
            }
            const int colp = nt * 8 + 2 * r;
            *(__half2*)&PhH[(size_t)(mw + q) * 72 + colp]     = __floats2half2_rn(p0, p1);
            *(__half2*)&PhH[(size_t)(mw + q + 8) * 72 + colp] = __floats2half2_rn(p2, p3);
        }
        l0 += ps0; l1 += ps1;
        __syncwarp();          // P is warp-private

        // ---- O += P @ V ------------------------------------------------------
#pragma unroll
        for (int ks = 0; ks < 4; ks++) {
            uint32_t afr[4];
            ldm_x4(afr, sbase + PH_OFF + (uint32_t)(mw + alr) * HROW
                         + (uint32_t)(ks * 32 + alc * 16));
#pragma unroll
            for (int dp = 0; dp < 4; dp++) {
                uint32_t tmp[4];
                ldm_x4_t(tmp, vB
                               + (uint32_t)(ks * 16 + (bg & 1) * 8 + blr) * HROW
                               + (uint32_t)(dp * 32 + (bg >> 1) * 16));
                mma_f16(O[dp * 2],     afr, tmp);
                mma_f16(O[dp * 2 + 1], afr, tmp + 2);
            }
        }
        // next iteration's top syncthreads covers buf reuse
    }

    // ---- finalize: reduce l over quad; store UNNORMALIZED O (fp32) + (m,l) --
    l0 += __shfl_xor_sync(0xffffffffu, l0, 1);
    l0 += __shfl_xor_sync(0xffffffffu, l0, 2);
    l1 += __shfl_xor_sync(0xffffffffu, l1, 1);
    l1 += __shfl_xor_sync(0xffffffffu, l1, 2);

    const int row0 = qb * 128 + mw + q;
#pragma unroll
    for (int nt = 0; nt < 8; nt++) {
        const int col = nt * 8 + 2 * r;
        *(float2*)(po + ((size_t)(row0 * BATCH + b)) * DMODEL + h * HDIM + col)
            = make_float2(O[nt][0], O[nt][1]);
        *(float2*)(po + ((size_t)((row0 + 8) * BATCH + b)) * DMODEL + h * HDIM + col)
            = make_float2(O[nt][2], O[nt][3]);
    }
    if (r == 0) {
        const size_t i0 = (((size_t)(row0 * BATCH + b)) * HEADS + h) * 2;
        mlp[i0]     = m0;
        mlp[i0 + 1] = l0;
        const size_t i1 = (((size_t)((row0 + 8) * BATCH + b)) * HEADS + h) * 2;
        mlp[i1]     = m1;
        mlp[i1 + 1] = l1;
    }
}

// ---------------- combine split-KV partials (4-way) -> fp16 av ---------------
__global__ void __launch_bounds__(256)
combine_kernel(const float* __restrict__ poAll, const float* __restrict__ mlAll,
               __half* __restrict__ out)
{
    const int row = blockIdx.x;          // = s*BATCH + b
    const int tid = threadIdx.x;
    const int d0 = tid * 4;
    const int h = d0 >> 6;

    float mv[NSPLIT], lv[NSPLIT];
    float M = -1e30f;
#pragma unroll
    for (int i = 0; i < NSPLIT; i++) {
        const float* mlp = mlAll + (size_t)i * ML_HALF + ((size_t)row * HEADS + h) * 2;
        mv[i] = mlp[0];
        lv[i] = mlp[1];
        M = fmaxf(M, mv[i]);
    }
    float w[NSPLIT], lsum = 0.f;
#pragma unroll
    for (int i = 0; i < NSPLIT; i++) {
        w[i] = __expf(mv[i] - M);
        lsum += lv[i] * w[i];
    }
    const float inv = 1.f / lsum;
#pragma unroll
    for (int i = 0; i < NSPLIT; i++) w[i] *= inv;

    float o0 = 0.f, o1 = 0.f, o2 = 0.f, o3 = 0.f;
#pragma unroll
    for (int i = 0; i < NSPLIT; i++) {
        const float4 a = *(const float4*)(poAll + (size_t)i * PO_HALF
                                          + (size_t)row * DMODEL + d0);
        o0 += a.x * w[i]; o1 += a.y * w[i];
        o2 += a.z * w[i]; o3 += a.w * w[i];
    }
    __half2 h01 = __floats2half2_rn(o0, o1);
    __half2 h23 = __floats2half2_rn(o2, o3);
    *(uint2*)(out + (size_t)row * DMODEL + d0)
        = make_uint2(*(uint32_t*)&h01, *(uint32_t*)&h23);
}

// ---------------- LayerNorm(a0 [+ a1] + res) * g + b -------------------------
__global__ void __launch_bounds__(256)
ln_kernel(const float* __restrict__ a0, const float* __restrict__ a1,
          const float* __restrict__ res,
          const float* __restrict__ g, const float* __restrict__ bta,
          float* __restrict__ out, __half* __restrict__ out_h)
{
    const int row = blockIdx.x;
    const int tid = threadIdx.x;
    const int lane = tid & 31, wrp = tid >> 5;
    __shared__ float red[8];
    __shared__ float bc;

    float vals[4];
    float s = 0.f;
    const float* ar = a0 + (size_t)row * DMODEL;
    const float* br = a1 ? a1 + (size_t)row * DMODEL : nullptr;
    const float* rr = res + (size_t)row * DMODEL;
#pragma unroll
    for (int i = 0; i < 4; i++) {
        int d = tid + i * 256;
        float v = ar[d] + rr[d];
        if (br) v += br[d];
        vals[i] = v;
        s += v;
    }
#pragma unroll
    for (int off = 16; off; off >>= 1) s += __shfl_xor_sync(0xffffffffu, s, off);
    if (lane == 0) red[wrp] = s;
    __syncthreads();
    if (tid == 0) {
        float t = 0.f;
#pragma unroll
        for (int w = 0; w < 8; w++) t += red[w];
        bc = t * (1.f / DMODEL);
    }
    __syncthreads();
    const float mu = bc;

    float vs = 0.f;
#pragma unroll
    for (int i = 0; i < 4; i++) {
        float dd = vals[i] - mu;
        vs += dd * dd;
    }
#pragma unroll
    for (int off = 16; off; off >>= 1) vs += __shfl_xor_sync(0xffffffffu, vs, off);
    __syncthreads();
    if (lane == 0) red[wrp] = vs;
    __syncthreads();
    if (tid == 0) {
        float t = 0.f;
#pragma unroll
        for (int w = 0; w < 8; w++) t += red[w];
        bc = rsqrtf(t * (1.f / DMODEL) + 1e-5f);
    }
    __syncthreads();
    const float rstd = bc;

    float* orow = out + (size_t)row * DMODEL;
    __half* hrow = out_h ? out_h + (size_t)row * DMODEL : nullptr;
#pragma unroll
    for (int i = 0; i < 4; i++) {
        int d = tid + i * 256;
        float vv = (vals[i] - mu) * rstd * g[d] + bta[d];
        orow[d] = vv;
        if (hrow) hrow[d] = __float2half(vv);
    }
}

// ---------------- launcher ---------------------------------------------------
extern "C" void kernel_launch(void* const* d_in, const int* in_sizes, int n_in,
                              void* d_out, int out_size)
{
    const float* x      = (const float*)d_in[0];
    const float* p      = (const float*)d_in[1];
    /* mask d_in[2] is analytic: unused */
    const float* memory = (const float*)d_in[3];
    const float* u_bias = (const float*)d_in[4];
    const float* v_bias = (const float*)d_in[5];
    const float* wq  = (const float*)d_in[6];
    const float* wke = (const float*)d_in[7];
    const float* wkr = (const float*)d_in[8];
    const float* wv  = (const float*)d_in[9];
    const float* wc  = (const float*)d_in[10];
    const float* w1  = (const float*)d_in[11];
    const float* w1b = (const float*)d_in[12];
    const float* w2  = (const float*)d_in[13];
    const float* w2b = (const float*)d_in[14];
    const float* ln1g = (const float*)d_in[15];
    const float* ln1b = (const float*)d_in[16];
    const float* ln2g = (const float*)d_in[17];
    const float* ln2b = (const float*)d_in[18];
    float* out = (float*)d_out;

    float *tbuf, *t2buf, *ubuf, *bias2, *poAll, *mlAll;
    __half *xh, *memh, *ph, *wqh, *wkeh, *wkrh, *wvh, *wch, *w1h, *w2h;
    __half *qh, *keh, *krh, *avh, *uh, *h1h, *kkh, *vh;
    cudaGetSymbolAddress((void**)&tbuf,  g_t);
    cudaGetSymbolAddress((void**)&t2buf, g_t2);
    cudaGetSymbolAddress((void**)&ubuf,  g_u);
    cudaGetSymbolAddress((void**)&poAll, g_po);
    cudaGetSymbolAddress((void**)&mlAll, g_ml);
    cudaGetSymbolAddress((void**)&xh,    g_xh);
    cudaGetSymbolAddress((void**)&memh,  g_memh);
    cudaGetSymbolAddress((void**)&ph,    g_ph);
    cudaGetSymbolAddress((void**)&wqh,   g_wqh);
    cudaGetSymbolAddress((void**)&wkeh,  g_wkeh);
    cudaGetSymbolAddress((void**)&wkrh,  g_wkrh);
    cudaGetSymbolAddress((void**)&wvh,   g_wvh);
    cudaGetSymbolAddress((void**)&wch,   g_wch);
    cudaGetSymbolAddress((void**)&w1h,   g_w1h);
    cudaGetSymbolAddress((void**)&w2h,   g_w2h);
    cudaGetSymbolAddress((void**)&qh,    g_qh);
    cudaGetSymbolAddress((void**)&keh,   g_keh);
    cudaGetSymbolAddress((void**)&krh,   g_krh);
    cudaGetSymbolAddress((void**)&avh,   g_avh);
    cudaGetSymbolAddress((void**)&uh,    g_uh);
    cudaGetSymbolAddress((void**)&h1h,   g_h1h);
    cudaGetSymbolAddress((void**)&kkh,   g_kkh);
    cudaGetSymbolAddress((void**)&vh,    g_vh);
    cudaGetSymbolAddress((void**)&bias2, g_bias);

    cudaFuncSetAttribute(gemm16_kernel,
                         cudaFuncAttributeMaxDynamicSharedMemorySize, GEMM16_SMEM);
    cudaFuncSetAttribute(flash16_kernel,
                         cudaFuncAttributeMaxDynamicSharedMemorySize, FLASH_SMEM);

    const dim3 blk(256);
    const size_t half = (size_t)ROWS_X * DMODEL;

    // ---- convert inputs + weights to fp16 (one merged launch) ---------------
    {
        CvtSegs cs{};
        int acc = 0, i = 0;
        auto add = [&](const float* s, __half* d, int n8) {
            cs.src[i] = s; cs.dst[i] = d; acc += n8; cs.end8[i] = acc; i++;
        };
        add(x,      xh,   ROWS_X * DMODEL / 8);
        add(memory, memh, ROWS_X * DMODEL / 8);
        add(p,      ph,   ROWS_T * DMODEL / 8);
        add(wq,  wqh,  DMODEL * DMODEL / 8);
        add(wke, wkeh, DMODEL * DMODEL / 8);
        add(wkr, wkrh, DMODEL * DMODEL / 8);
        add(wv,  wvh,  DMODEL * DMODEL / 8);
        add(wc,  wch,  DMODEL * DMODEL / 8);
        add(w1,  w1h,  FFDIM * DMODEL / 8);
        add(w2,  w2h,  FFDIM * DMODEL / 8);
        cs.nseg = i;
        cvt_all_kernel<<<(acc + 255) / 256, blk>>>(cs, acc);
    }

    // ---- all 6 projections in ONE persistent launch (tiles 8x16x7) ----------
    // V slices (z=2, z=4) write DIRECTLY into the flash V layout [b,h,t,64].
    {
        GemmPtrs gp{};
        gp.A[0] = xh;   gp.W[0] = wqh;  gp.Ch[0] = qh;
        gp.A[1] = xh;   gp.W[1] = wkeh; gp.Ch[1] = keh + half;
        gp.A[2] = xh;   gp.W[2] = wvh;  gp.Ch[2] = vh;  gp.voff[2] = S_LEN;
        gp.A[3] = memh; gp.W[3] = wkeh; gp.Ch[3] = keh;
        gp.A[4] = memh; gp.W[4] = wvh;  gp.Ch[4] = vh;  gp.voff[4] = 0;
        gp.A[5] = ph;        gp.W[5] = wkrh; gp.Ch[5] = krh;
        gp.A[6] = ph + half; gp.W[6] = wkrh; gp.Ch[6] = krh + half;
        gemm16_kernel<<<PERSIST_CTAS, blk, GEMM16_SMEM>>>(
            gp, ROWS_X, DMODEL, DMODEL, DMODEL, 0, (1 << 2) | (1 << 4),
            8, 16, 7);
    }

    // prep: fuse KK (fp16), bias (fp32, pre-scaled)
    prep_kernel<<<ROWS_T, blk>>>(keh, krh, u_bias, v_bias, kkh, bias2);

    // split-KV x4 fp16 flash attention + combine
    flash16_kernel<<<dim3(32, HEADS, BATCH), blk, FLASH_SMEM>>>(
        qh, kkh, vh, bias2, poAll, mlAll);
    combine_kernel<<<ROWS_X, blk>>>(poAll, mlAll, avh);

    // output proj (split-K=2) + LN1 (fused add; emits uh fp16)
    {
        GemmPtrs gp{};
        gp.A[0] = avh;       gp.W[0] = wch;       gp.C[0] = tbuf;
        gp.A[1] = avh + 512; gp.W[1] = wch + 512; gp.C[1] = t2buf;
        gemm16_kernel<<<256, blk, GEMM16_SMEM>>>(
            gp, ROWS_X, DMODEL, 512, DMODEL, 0, 0, 8, 16, 2);
    }
    ln_kernel<<<ROWS_X, blk>>>(tbuf, t2buf, x, ln1g, ln1b, ubuf, uh);

    // FFN: w1 (relu, fp16 out, persistent), w2 (split-K=2) + LN2 (fused add)
    {
        GemmPtrs gp{};
        gp.A[0] = uh; gp.W[0] = w1h; gp.Ch[0] = h1h; gp.bias[0] = w1b;
        gemm16_kernel<<<PERSIST_CTAS, blk, GEMM16_SMEM>>>(
            gp, ROWS_X, FFDIM, DMODEL, DMODEL, 1, 0, 32, 16, 1);
    }
    {
        GemmPtrs gp{};
        gp.A[0] = h1h;        gp.W[0] = w2h;        gp.C[0] = tbuf;  gp.bias[0] = w2b;
        gp.A[1] = h1h + 2048; gp.W[1] = w2h + 2048; gp.C[1] = t2buf;
        gemm16_kernel<<<256, blk, GEMM16_SMEM>>>(
            gp, ROWS_X, DMODEL, 2048, FFDIM, 0, 0, 8, 16, 2);
    }
    ln_kernel<<<ROWS_X, blk>>>(tbuf, t2buf, ubuf, ln2g, ln2b, out, nullptr);
}